// round 1
// baseline (speedup 1.0000x reference)
#include <cuda_runtime.h>
#include <cuda_bf16.h>

// GraphTrainNN: out[b] = prod_g  w2[g] * (w1[g]^2 + w0[g]*x[b,g]^2) / (w1[g]^2 + x[b,g]^2)
// B = 524288 rows, G = 127 genes. x: (B,G) fp32, w: (G,3) fp32 [w0, w1, w2].
//
// Strategy: warp-per-row. Lane l owns genes l, l+32, l+64, l+96 (gene 127 does
// not exist -> identity terms). Accumulate numerator/denominator PRODUCTS and
// divide only once per 16-gene chunk (after 2 butterfly steps) to keep MUFU
// off the critical path and partial products out of the denormal range.
// prod(w2) over all genes is row-invariant -> computed once per warp.

#ifndef GG
#define GG 127
#endif

__global__ __launch_bounds__(256, 8)
void hill_prod_kernel(const float* __restrict__ x,
                      const float* __restrict__ w,
                      float* __restrict__ out,
                      int rows)
{
    const int lane   = threadIdx.x & 31;
    const int warp   = (blockIdx.x * blockDim.x + threadIdx.x) >> 5;
    const int nwarps = (gridDim.x * blockDim.x) >> 5;

    // ---- per-lane gene parameters (loaded once, reused for all rows) ----
    float w0c[4], wnc[4];
    float w2l = 1.0f;
#pragma unroll
    for (int j = 0; j < 4; ++j) {
        const int g = lane + 32 * j;
        if (g < GG) {
            const float a = __ldg(&w[g * 3 + 0]);   // fold
            const float k = __ldg(&w[g * 3 + 1]);   // half-sat
            const float s = __ldg(&w[g * 3 + 2]);   // scale
            w0c[j] = a;
            wnc[j] = k * k;                          // k^n, n=2
            w2l   *= s;
        } else {
            // identity gene: with xv forced to 0 below, num term = wn = 1,
            // den term = wn + 0 = 1.
            w0c[j] = 0.0f;
            wnc[j] = 1.0f;
        }
    }
    // full-warp product of w2 (row-invariant constant)
#pragma unroll
    for (int o = 16; o; o >>= 1)
        w2l *= __shfl_xor_sync(0xFFFFFFFFu, w2l, o);
    const float W2ALL = w2l;

    // ---- row loop ----
    for (int row = warp; row < rows; row += nwarps) {
        const float* __restrict__ xr = x + (size_t)row * GG;

        float num = 1.0f, den = 1.0f;
#pragma unroll
        for (int j = 0; j < 4; ++j) {
            const int g  = lane + 32 * j;
            const float xv = (g < GG) ? __ldg(xr + g) : 0.0f;
            const float xn = xv * xv;
            num *= fmaf(w0c[j], xn, wnc[j]);   // wn + w0*x^n
            den *= (wnc[j] + xn);              // wn + x^n
        }

        // butterfly to 4-lane groups: each lane now holds a 16-gene product.
        // Min possible term is ~0.01 -> 0.01^16 = 1e-32, still fp32-normal.
#pragma unroll
        for (int o = 1; o <= 2; o <<= 1) {
            num *= __shfl_xor_sync(0xFFFFFFFFu, num, o);
            den *= __shfl_xor_sync(0xFFFFFFFFu, den, o);
        }

        // single division per row (warp-wide, redundant across groups is fine)
        float r = __fdividef(num, den);

        // finish the product over the 8 chunks of 16 genes
#pragma unroll
        for (int o = 4; o <= 16; o <<= 1)
            r *= __shfl_xor_sync(0xFFFFFFFFu, r, o);

        if (lane == 0)
            out[row] = W2ALL * r;
    }
}

extern "C" void kernel_launch(void* const* d_in, const int* in_sizes, int n_in,
                              void* d_out, int out_size)
{
    const float* x = (const float*)d_in[0];   // (B, G) fp32
    const float* w = (const float*)d_in[1];   // (G, 3) fp32
    float* out = (float*)d_out;               // (B, 1) fp32

    const int rows = in_sizes[0] / GG;        // 524288

    // 16384 warps -> 32 rows per warp (amortizes the parameter preload),
    // 2048 blocks x 256 threads.
    const int threads = 256;
    const int blocks  = 2048;
    hill_prod_kernel<<<blocks, threads>>>(x, w, out, rows);
}

// round 2
// speedup vs baseline: 1.0532x; 1.0532x over previous
#include <cuda_runtime.h>
#include <cuda_bf16.h>

// GraphTrainNN: out[b] = prod_g  w2[g] * (w1[g]^2 + w0[g]*x[b,g]^2) / (w1[g]^2 + x[b,g]^2)
// B = 524288 rows, G = 127 genes. x: (B,G) fp32, w: (G,3) fp32 [w0, w1, w2].
//
// R2: warp-per-row, TWO rows per loop iteration.
//  - 8 independent LDGs in flight per warp (row pair is 1016 contiguous bytes).
//  - per-lane 4-gene ratio + single fast division, then 5 shuffle-mul levels;
//    two independent reduction chains (one per row) interleave for ILP.
//  - prod(w2) is row-invariant, computed once per warp.

#ifndef GG
#define GG 127
#endif

__global__ __launch_bounds__(256)
void hill_prod2_kernel(const float* __restrict__ x,
                       const float* __restrict__ w,
                       float* __restrict__ out,
                       int rows)
{
    const int lane   = threadIdx.x & 31;
    const int warp   = (blockIdx.x * blockDim.x + threadIdx.x) >> 5;
    const int nwarps = (gridDim.x * blockDim.x) >> 5;

    // ---- per-lane gene parameters (loaded once, reused for all rows) ----
    float w0c[4], wnc[4];
    float w2l = 1.0f;
#pragma unroll
    for (int j = 0; j < 4; ++j) {
        const int g = lane + 32 * j;
        if (g < GG) {
            const float a = __ldg(&w[g * 3 + 0]);   // fold
            const float k = __ldg(&w[g * 3 + 1]);   // half-sat
            const float s = __ldg(&w[g * 3 + 2]);   // scale
            w0c[j] = a;
            wnc[j] = k * k;                          // k^n, n=2
            w2l   *= s;
        } else {
            // identity gene: xv forced to 0 -> num term = 1, den term = 1
            w0c[j] = 0.0f;
            wnc[j] = 1.0f;
        }
    }
#pragma unroll
    for (int o = 16; o; o >>= 1)
        w2l *= __shfl_xor_sync(0xFFFFFFFFu, w2l, o);
    const float W2ALL = w2l;

    // ---- row-pair loop ----
    for (int base = warp * 2; base < rows; base += 2 * nwarps) {
        const float* __restrict__ xr0 = x + (size_t)base * GG;
        const float* __restrict__ xr1 = xr0 + GG;      // base+1 (rows is even)

        // issue all 8 loads up front
        float xv0[4], xv1[4];
#pragma unroll
        for (int j = 0; j < 4; ++j) {
            const int g = lane + 32 * j;
            xv0[j] = (g < GG) ? __ldg(xr0 + g) : 0.0f;
            xv1[j] = (g < GG) ? __ldg(xr1 + g) : 0.0f;
        }

        float n0 = 1.0f, d0 = 1.0f, n1 = 1.0f, d1 = 1.0f;
#pragma unroll
        for (int j = 0; j < 4; ++j) {
            const float a0 = xv0[j] * xv0[j];
            const float a1 = xv1[j] * xv1[j];
            n0 *= fmaf(w0c[j], a0, wnc[j]);
            d0 *= (wnc[j] + a0);
            n1 *= fmaf(w0c[j], a1, wnc[j]);
            d1 *= (wnc[j] + a1);
        }

        // per-lane 4-gene ratio: num<=den (w0<=1), ratio in [~1e-4, 1] -> safe
        float r0 = __fdividef(n0, d0);
        float r1 = __fdividef(n1, d1);

        // 32-lane product, two chains interleaved
#pragma unroll
        for (int o = 1; o <= 16; o <<= 1) {
            r0 *= __shfl_xor_sync(0xFFFFFFFFu, r0, o);
            r1 *= __shfl_xor_sync(0xFFFFFFFFu, r1, o);
        }

        if (lane == 0) {
            out[base]     = W2ALL * r0;
            out[base + 1] = W2ALL * r1;
        }
    }
}

extern "C" void kernel_launch(void* const* d_in, const int* in_sizes, int n_in,
                              void* d_out, int out_size)
{
    const float* x = (const float*)d_in[0];   // (B, G) fp32
    const float* w = (const float*)d_in[1];   // (G, 3) fp32
    float* out = (float*)d_out;               // (B, 1) fp32

    const int rows = in_sizes[0] / GG;        // 524288

    // 16384 warps -> 16 row-pairs per warp (amortizes the parameter preload)
    const int threads = 256;
    const int blocks  = 2048;
    hill_prod2_kernel<<<blocks, threads>>>(x, w, out, rows);
}

// round 3
// speedup vs baseline: 1.1708x; 1.1116x over previous
#include <cuda_runtime.h>
#include <cuda_bf16.h>

// GraphTrainNN: out[b] = prod_g  w2[g] * (w1[g]^2 + w0[g]*x[b,g]^2) / (w1[g]^2 + x[b,g]^2)
// B = 524288 rows, G = 127 genes. x: (B,G) fp32, w: (G,3) fp32 [w0, w1, w2].
//
// R3: warp-per-row, FOUR rows per loop iteration.
//  - 16 independent LDGs in flight per warp iteration (4x MLP of R1).
//  - per-lane 4-gene ratio + single fast division per row, then 5 shuffle-mul
//    levels with FOUR independent chains (ILP hides SHFL latency); tail cost
//    amortized over 4 rows.
//  - float4 packed output store (row group is 16B aligned).
//  - launch_bounds(256,4) gives ptxas a 64-reg budget so all loads stay live.

#ifndef GG
#define GG 127
#endif

__global__ __launch_bounds__(256, 4)
void hill_prod4_kernel(const float* __restrict__ x,
                       const float* __restrict__ w,
                       float* __restrict__ out,
                       int rows)
{
    const int lane   = threadIdx.x & 31;
    const int warp   = (blockIdx.x * blockDim.x + threadIdx.x) >> 5;
    const int nwarps = (gridDim.x * blockDim.x) >> 5;

    // ---- per-lane gene parameters (loaded once, reused for all rows) ----
    float w0c[4], wnc[4];
    float w2l = 1.0f;
#pragma unroll
    for (int j = 0; j < 4; ++j) {
        const int g = lane + 32 * j;
        if (g < GG) {
            const float a = __ldg(&w[g * 3 + 0]);   // fold
            const float k = __ldg(&w[g * 3 + 1]);   // half-sat
            const float s = __ldg(&w[g * 3 + 2]);   // scale
            w0c[j] = a;
            wnc[j] = k * k;                          // k^n, n=2
            w2l   *= s;
        } else {
            w0c[j] = 0.0f;   // identity gene (xv forced to 0): num=den=1
            wnc[j] = 1.0f;
        }
    }
#pragma unroll
    for (int o = 16; o; o >>= 1)
        w2l *= __shfl_xor_sync(0xFFFFFFFFu, w2l, o);
    const float W2ALL = w2l;

    // ---- 4-row loop ----
    for (int base = warp * 4; base < rows; base += 4 * nwarps) {
        const float* __restrict__ xr = x + (size_t)base * GG;

        // issue all 16 loads up front (independent -> MLP = 16)
        float xv[4][4];
#pragma unroll
        for (int r = 0; r < 4; ++r) {
#pragma unroll
            for (int j = 0; j < 4; ++j) {
                const int g = lane + 32 * j;
                xv[r][j] = (g < GG) ? __ldg(xr + r * GG + g) : 0.0f;
            }
        }

        float num[4], den[4];
#pragma unroll
        for (int r = 0; r < 4; ++r) { num[r] = 1.0f; den[r] = 1.0f; }

#pragma unroll
        for (int j = 0; j < 4; ++j) {
#pragma unroll
            for (int r = 0; r < 4; ++r) {
                const float a = xv[r][j] * xv[r][j];
                num[r] *= fmaf(w0c[j], a, wnc[j]);   // wn + w0*x^n
                den[r] *= (wnc[j] + a);              // wn + x^n
            }
        }

        // per-lane 4-gene ratio: num<=den scale-wise, ratio in [~1e-4, 1]
        float rr[4];
#pragma unroll
        for (int r = 0; r < 4; ++r)
            rr[r] = __fdividef(num[r], den[r]);

        // 32-lane product, four independent chains interleaved
#pragma unroll
        for (int o = 1; o <= 16; o <<= 1) {
#pragma unroll
            for (int r = 0; r < 4; ++r)
                rr[r] *= __shfl_xor_sync(0xFFFFFFFFu, rr[r], o);
        }

        if (lane == 0) {
            float4 o4;
            o4.x = W2ALL * rr[0];
            o4.y = W2ALL * rr[1];
            o4.z = W2ALL * rr[2];
            o4.w = W2ALL * rr[3];
            *reinterpret_cast<float4*>(out + base) = o4;   // base % 4 == 0
        }
    }
}

extern "C" void kernel_launch(void* const* d_in, const int* in_sizes, int n_in,
                              void* d_out, int out_size)
{
    const float* x = (const float*)d_in[0];   // (B, G) fp32
    const float* w = (const float*)d_in[1];   // (G, 3) fp32
    float* out = (float*)d_out;               // (B, 1) fp32

    const int rows = in_sizes[0] / GG;        // 524288

    // 16384 warps -> 8 quad-row iterations per warp
    const int threads = 256;
    const int blocks  = 2048;
    hill_prod4_kernel<<<blocks, threads>>>(x, w, out, rows);
}

// round 4
// speedup vs baseline: 1.1716x; 1.0007x over previous
#include <cuda_runtime.h>
#include <cuda_bf16.h>

// GraphTrainNN: out[b] = prod_g  w2[g] * (w1[g]^2 + w0[g]*x[b,g]^2) / (w1[g]^2 + x[b,g]^2)
// B = 524288 rows, G = 127 genes. x: (B,G) fp32, w: (G,3) fp32 [w0, w1, w2].
//
// R4: warp-per-row, 4 rows/iter, SOFTWARE-PIPELINED (register double buffer).
//  - Loads for iteration i+1 are issued before computing iteration i, so the
//    compute + 5-level shuffle-reduce tail always has 16 LDGs in flight.
//  - Ping-pong buffers via manual 2x unroll (no register copies).
//  - float4 packed output store; prod(w2) hoisted per warp.

#ifndef GG
#define GG 127
#endif

__global__ __launch_bounds__(256, 4)
void hill_pipe_kernel(const float* __restrict__ x,
                      const float* __restrict__ w,
                      float* __restrict__ out,
                      int rows)
{
    const int lane   = threadIdx.x & 31;
    const int warp   = (blockIdx.x * blockDim.x + threadIdx.x) >> 5;
    const int nwarps = (gridDim.x * blockDim.x) >> 5;
    const int stride = 4 * nwarps;

    // ---- per-lane gene parameters (loaded once) ----
    float w0c[4], wnc[4];
    float w2l = 1.0f;
#pragma unroll
    for (int j = 0; j < 4; ++j) {
        const int g = lane + 32 * j;
        if (g < GG) {
            const float a = __ldg(&w[g * 3 + 0]);
            const float k = __ldg(&w[g * 3 + 1]);
            const float s = __ldg(&w[g * 3 + 2]);
            w0c[j] = a;
            wnc[j] = k * k;
            w2l   *= s;
        } else {
            w0c[j] = 0.0f;   // identity gene: num=den=1
            wnc[j] = 1.0f;
        }
    }
#pragma unroll
    for (int o = 16; o; o >>= 1)
        w2l *= __shfl_xor_sync(0xFFFFFFFFu, w2l, o);
    const float W2ALL = w2l;

    // ---- helpers ----
    auto load4 = [&](float (&xv)[4][4], int base) {
        const float* __restrict__ xr = x + (size_t)base * GG;
#pragma unroll
        for (int r = 0; r < 4; ++r)
#pragma unroll
            for (int j = 0; j < 4; ++j) {
                const int g = lane + 32 * j;
                xv[r][j] = (g < GG) ? __ldg(xr + r * GG + g) : 0.0f;
            }
    };

    auto compute4 = [&](const float (&xv)[4][4], int base) {
        float num[4], den[4];
#pragma unroll
        for (int r = 0; r < 4; ++r) { num[r] = 1.0f; den[r] = 1.0f; }
#pragma unroll
        for (int j = 0; j < 4; ++j)
#pragma unroll
            for (int r = 0; r < 4; ++r) {
                const float a = xv[r][j] * xv[r][j];
                num[r] *= fmaf(w0c[j], a, wnc[j]);
                den[r] *= (wnc[j] + a);
            }
        float rr[4];
#pragma unroll
        for (int r = 0; r < 4; ++r)
            rr[r] = __fdividef(num[r], den[r]);   // ratio in [~1e-4, 1]
#pragma unroll
        for (int o = 1; o <= 16; o <<= 1)
#pragma unroll
            for (int r = 0; r < 4; ++r)
                rr[r] *= __shfl_xor_sync(0xFFFFFFFFu, rr[r], o);
        if (lane == 0) {
            float4 o4;
            o4.x = W2ALL * rr[0];
            o4.y = W2ALL * rr[1];
            o4.z = W2ALL * rr[2];
            o4.w = W2ALL * rr[3];
            *reinterpret_cast<float4*>(out + base) = o4;   // base % 4 == 0
        }
    };

    // ---- pipelined loop (ping-pong, no copies) ----
    int base = warp * 4;
    if (base >= rows) return;

    float bufA[4][4], bufB[4][4];
    load4(bufA, base);

    for (;;) {
        int nxt = base + stride;
        if (nxt < rows) load4(bufB, nxt);      // prefetch while A computes
        compute4(bufA, base);
        base = nxt;
        if (base >= rows) break;

        nxt = base + stride;
        if (nxt < rows) load4(bufA, nxt);      // prefetch while B computes
        compute4(bufB, base);
        base = nxt;
        if (base >= rows) break;
    }
}

extern "C" void kernel_launch(void* const* d_in, const int* in_sizes, int n_in,
                              void* d_out, int out_size)
{
    const float* x = (const float*)d_in[0];   // (B, G) fp32
    const float* w = (const float*)d_in[1];   // (G, 3) fp32
    float* out = (float*)d_out;               // (B, 1) fp32

    const int rows = in_sizes[0] / GG;        // 524288

    const int threads = 256;
    const int blocks  = 2048;                 // 16384 warps, 8 iters each
    hill_pipe_kernel<<<blocks, threads>>>(x, w, out, rows);
}